// round 14
// baseline (speedup 1.0000x reference)
#include <cuda_runtime.h>

// ---------------------------------------------------------------------------
// FastRx_wo_Diag fp32. Round 12: forked graph — light front chain (emb, qkv,
// gk, query) on a side stream overlapping the heavy GCN spine (k1->k2->k3);
// k1 widened to 512 threads (8-way gather split, shorter chains).
// ---------------------------------------------------------------------------

#define RCAP 128
#define NV   64
#define VMED 4000

// ------------------------------ scratch ------------------------------------
__device__ float g_x[NV * 128];
__device__ float g_q[NV * 256];
__device__ float g_k[NV * 256];
__device__ float g_v[NV * 256];
__device__ float g_gk[256];
__device__ float g_query[256];
__device__ __align__(16) float g_vsp[NV * 4];

__device__ float g_ellval[2][VMED * RCAP];
__device__ int   g_ellcol[2][VMED * RCAP];
__device__ int   g_elln[2][VMED];
__device__ float g_h[2][VMED * 256];
__device__ float g_t[2][VMED * 256];
__device__ float g_dm[VMED * 256];

__device__ float g_f1p[125][256];
__device__ float g_esum[125];
__device__ float g_m[125];
__device__ float g_f2p[63][256];
__device__ float g_hid[512];
__device__ float g_sp[VMED];
__device__ float g_negp[32];
__device__ int   g_ctr;

// ------------------------------ helpers ------------------------------------
__device__ __forceinline__ float warp_sum(float v) {
    #pragma unroll
    for (int o = 16; o; o >>= 1) v += __shfl_xor_sync(0xffffffffu, v, o);
    return v;
}
__device__ __forceinline__ float warp_max(float v) {
    #pragma unroll
    for (int o = 16; o; o >>= 1) v = fmaxf(v, __shfl_xor_sync(0xffffffffu, v, o));
    return v;
}
__device__ __forceinline__ unsigned long long dup2(float x) {
    unsigned long long r;
    asm("mov.b64 %0, {%1, %1};" : "=l"(r) : "f"(x));
    return r;
}
__device__ __forceinline__ float2 unp2(unsigned long long v) {
    float2 f;
    asm("mov.b64 {%0, %1}, %2;" : "=f"(f.x), "=f"(f.y) : "l"(v));
    return f;
}
#define FMA2(acc, a, b) asm("fma.rn.f32x2 %0, %1, %2, %0;" : "+l"(acc) : "l"(a), "l"(b))

// ============================================================================
// Branch B1: embedding mean + conv   (64 blocks x 128)
// ============================================================================
__global__ void __launch_bounds__(128) kb_emb(
    const int* __restrict__ pc, const float* __restrict__ emb,
    const float* __restrict__ cw, const float* __restrict__ cb) {
    __shared__ float xm[130];
    __shared__ int cs[32];
    int v = blockIdx.x, f = threadIdx.x;
    if (f < 32) cs[f] = pc[v * 32 + f];
    __syncthreads();
    float a = 0.f;
    #pragma unroll 4
    for (int k = 0; k < 32; k++) a += emb[cs[k] * 128 + f];
    xm[f + 1] = a * (1.f / 32.f);
    if (f == 0) { xm[0] = 0.f; xm[129] = 0.f; }
    __syncthreads();
    float w0 = cw[0], w1 = cw[1], w2 = cw[2], b = cb[0];
    g_x[v * 128 + f] = fmaxf(w0 * xm[f] + w1 * xm[f + 1] + w2 * xm[f + 2] + b, 0.f);
}

// ============================================================================
// Branch B2: q,k,v = x @ W   (192 blocks x 256)
// ============================================================================
__global__ void __launch_bounds__(256) kb_qkv(
    const float* __restrict__ wq, const float* __restrict__ wk,
    const float* __restrict__ wv) {
    __shared__ float xr[128];
    int b2 = blockIdx.x, v = b2 & 63, m = b2 >> 6, t = threadIdx.x;
    const float* W = (m == 0) ? wq : (m == 1) ? wk : wv;
    float* D = (m == 0) ? g_q : (m == 1) ? g_k : g_v;
    if (t < 128) xr[t] = g_x[v * 128 + t];
    __syncthreads();
    float a0 = 0.f, a1 = 0.f, a2 = 0.f, a3 = 0.f;
    #pragma unroll 8
    for (int f = 0; f < 128; f += 4) {
        a0 += xr[f]     * W[(f)     * 256 + t];
        a1 += xr[f + 1] * W[(f + 1) * 256 + t];
        a2 += xr[f + 2] * W[(f + 2) * 256 + t];
        a3 += xr[f + 3] * W[(f + 3) * 256 + t];
    }
    D[v * 256 + t] = (a0 + a1) + (a2 + a3);
}

// ============================================================================
// Branch B3: fastformer global vectors   (1 block x 256)
// ============================================================================
__global__ void __launch_bounds__(256) kb_gk(
    const float* __restrict__ alpha, const float* __restrict__ beta) {
    __shared__ float m1[64], rd1[64], gqs[256], m2[64], rd2[64];
    const float scale = 0.0625f;
    int t = threadIdx.x, lane = t & 31, w = t >> 5;
    for (int rr = 0; rr < 8; rr++) {
        int r = w * 8 + rr;
        float z[8], mx = -1e30f;
        #pragma unroll
        for (int j = 0; j < 8; j++) {
            int e = lane + j * 32;
            z[j] = g_q[r * 256 + e] * alpha[e] * scale;
            mx = fmaxf(mx, z[j]);
        }
        mx = warp_max(mx);
        float s = 0.f;
        #pragma unroll
        for (int j = 0; j < 8; j++) s += expf(z[j] - mx);
        s = warp_sum(s);
        if (lane == 0) { m1[r] = mx; rd1[r] = 1.f / s; }
    }
    __syncthreads();
    {
        float a = alpha[t] * scale, acc = 0.f;
        for (int v = 0; v < 64; v++) {
            float q = g_q[v * 256 + t];
            acc += q * expf(q * a - m1[v]) * rd1[v];
        }
        gqs[t] = acc;
    }
    __syncthreads();
    for (int rr = 0; rr < 8; rr++) {
        int r = w * 8 + rr;
        float z[8], mx = -1e30f;
        #pragma unroll
        for (int j = 0; j < 8; j++) {
            int e = lane + j * 32;
            z[j] = gqs[e] * g_k[r * 256 + e] * beta[e] * scale;
            mx = fmaxf(mx, z[j]);
        }
        mx = warp_max(mx);
        float s = 0.f;
        #pragma unroll
        for (int j = 0; j < 8; j++) s += expf(z[j] - mx);
        s = warp_sum(s);
        if (lane == 0) { m2[r] = mx; rd2[r] = 1.f / s; }
    }
    __syncthreads();
    {
        float bsc = beta[t] * scale, gq_e = gqs[t], acc = 0.f;
        for (int v = 0; v < 64; v++) {
            float p = gq_e * g_k[v * 256 + t];
            acc += p * expf(p * bsc - m2[v]) * rd2[v];
        }
        g_gk[t] = acc;
    }
}

// ============================================================================
// Branch B4: feat cols + visit-score partials (256 blocks = 64 v x 4 chunks)
// ============================================================================
__global__ void __launch_bounds__(256) k4_feat(const float* __restrict__ wr) {
    __shared__ float gvr[256], gv63[256];
    __shared__ float pf[4][64], p63[4][64];
    __shared__ float red[2];
    int bid = blockIdx.x;
    int v = bid >> 2, ch = bid & 3;
    int t = threadIdx.x;
    {
        float gk = g_gk[t];
        gvr[t]  = gk * g_v[v * 256 + t];
        gv63[t] = gk * g_v[63 * 256 + t];
    }
    __syncthreads();
    int col = (ch << 6) + (t & 63), seg = t >> 6;
    float a = 0.f, b = 0.f;
    int e0 = seg * 64;
    #pragma unroll 8
    for (int e = e0; e < e0 + 64; e++) {
        float wv = wr[e * 256 + col];
        a += gvr[e] * wv;
        b += gv63[e] * wv;
    }
    pf[seg][t & 63] = a; p63[seg][t & 63] = b;
    __syncthreads();
    if (t < 64) {
        int c = (ch << 6) + t;
        float fr  = g_q[v * 256 + c]  + ((pf[0][t] + pf[1][t]) + (pf[2][t] + pf[3][t]));
        float f63 = g_q[63 * 256 + c] + ((p63[0][t] + p63[1][t]) + (p63[2][t] + p63[3][t]));
        if (v == 63) g_query[c] = fr;
        float p = warp_sum(fr * f63);
        if ((t & 31) == 0) red[t >> 5] = p;
    }
    __syncthreads();
    if (t == 0) g_vsp[v * 4 + ch] = red[0] + red[1];
}

// ============================================================================
// A1: adjacency scan -> ELL + h = relu(A@w1+b1)   (8000 blocks x 512)
// ============================================================================
__global__ void __launch_bounds__(512) k1_scan(
    const float* __restrict__ ehr_adj, const float* __restrict__ ddi_adj,
    const float* __restrict__ ehr_w1, const float* __restrict__ ehr_b1,
    const float* __restrict__ ddi_w1, const float* __restrict__ ddi_b1) {

    __shared__ float val_s[RCAP];
    __shared__ int   col_s[RCAP];
    __shared__ int   woff[16];
    __shared__ int   nnz_s;
    __shared__ float4 part[512];

    int bid = blockIdx.x;
    int t = threadIdx.x, lane = t & 31, w = t >> 5;

    int mat = (bid >= VMED) ? 1 : 0;
    int r = bid - mat * VMED;
    const float* adj = mat ? ddi_adj : ehr_adj;
    const float* w1  = mat ? ddi_w1  : ehr_w1;
    const float* b1  = mat ? ddi_b1  : ehr_b1;

    // --- scan 8 floats per thread (threads 0..499 cover 4000) ---
    float arr[8];
    int cnt = 0;
    const float4* rowp = (const float4*)(adj + (size_t)r * 4000);
    if (t < 500) {
        #pragma unroll
        for (int j = 0; j < 2; j++) {
            float4 q = rowp[t * 2 + j];
            arr[j * 4 + 0] = q.x; arr[j * 4 + 1] = q.y;
            arr[j * 4 + 2] = q.z; arr[j * 4 + 3] = q.w;
        }
        #pragma unroll
        for (int j = 0; j < 8; j++) cnt += (arr[j] != 0.f);
    }
    int incl = cnt;
    #pragma unroll
    for (int o = 1; o < 32; o <<= 1) {
        int x = __shfl_up_sync(0xffffffffu, incl, o);
        if (lane >= o) incl += x;
    }
    if (lane == 31) woff[w] = incl;
    __syncthreads();
    if (t == 0) {
        int s = 0;
        #pragma unroll
        for (int i = 0; i < 16; i++) { int c = woff[i]; woff[i] = s; s += c; }
        nnz_s = (s < RCAP) ? s : RCAP;
    }
    __syncthreads();
    int pos = woff[w] + incl - cnt;
    if (t < 500) {
        #pragma unroll
        for (int j = 0; j < 8; j++) {
            float vv = arr[j];
            if (vv != 0.f) {
                if (pos < RCAP) { val_s[pos] = vv; col_s[pos] = t * 8 + j; }
                pos++;
            }
        }
    }
    __syncthreads();
    int n = nnz_s;
    for (int i = t; i < n; i += 512) {
        g_ellval[mat][r * RCAP + i] = val_s[i];
        g_ellcol[mat][r * RCAP + i] = col_s[i];
    }
    if (t == 0) g_elln[mat][r] = n;

    // --- h = relu(spmm + b1): 8 nnz segments x 64 col-quads -----------------
    int eg = (t & 63) << 2;
    int seg = t >> 6;
    float4 acc = {0.f, 0.f, 0.f, 0.f};
    int i0 = (n * seg) >> 3, i1 = (n * (seg + 1)) >> 3;
    for (int i = i0; i < i1; i++) {
        float vv = val_s[i];
        const float4 wv = *(const float4*)(w1 + (size_t)col_s[i] * 256 + eg);
        acc.x += vv * wv.x; acc.y += vv * wv.y; acc.z += vv * wv.z; acc.w += vv * wv.w;
    }
    part[t] = acc;
    __syncthreads();
    if (seg == 0) {
        float4 p0 = part[t],       p1 = part[t + 64],  p2 = part[t + 128], p3 = part[t + 192];
        float4 p4 = part[t + 256], p5 = part[t + 320], p6 = part[t + 384], p7 = part[t + 448];
        float4 bb = *(const float4*)(b1 + eg);
        float4 hh;
        hh.x = fmaxf(((p0.x + p1.x) + (p2.x + p3.x)) + ((p4.x + p5.x) + (p6.x + p7.x)) + bb.x, 0.f);
        hh.y = fmaxf(((p0.y + p1.y) + (p2.y + p3.y)) + ((p4.y + p5.y) + (p6.y + p7.y)) + bb.y, 0.f);
        hh.z = fmaxf(((p0.z + p1.z) + (p2.z + p3.z)) + ((p4.z + p5.z) + (p6.z + p7.z)) + bb.z, 0.f);
        hh.w = fmaxf(((p0.w + p1.w) + (p2.w + p3.w)) + ((p4.w + p5.w) + (p6.w + p7.w)) + bb.w, 0.f);
        *(float4*)(g_h[mat] + (size_t)r * 256 + eg) = hh;
    }
}

// ============================================================================
// A2: t = h @ w2 GEMM, M=32/block, w2 slab staged in smem  (250 blocks x 256)
// ============================================================================
__global__ void __launch_bounds__(256) k2_gemm(
    const float* __restrict__ ehr_w2, const float* __restrict__ ddi_w2) {
    extern __shared__ float dynsm[];
    int t = threadIdx.x, bid = blockIdx.x;

    float* hs  = dynsm;                 // 32*256 floats
    float* w2s = dynsm + 32 * 256;      // 64*256 floats
    int mat = bid / 125, r0 = (bid % 125) * 32;
    const float* w2 = mat ? ddi_w2 : ehr_w2;

    {
        const float4* src = (const float4*)(g_h[mat] + (size_t)r0 * 256);
        float4* dst = (float4*)hs;
        #pragma unroll
        for (int j = 0; j < 8; j++) dst[t + j * 256] = src[t + j * 256];
    }

    int cg = t & 31, rg = t >> 5;
    int rbase = rg * 4;
    unsigned long long acc[4][4];
    #pragma unroll
    for (int a = 0; a < 4; a++)
        #pragma unroll
        for (int b = 0; b < 4; b++) acc[a][b] = 0ULL;

    #pragma unroll 1
    for (int kc = 0; kc < 4; kc++) {
        __syncthreads();
        {
            const float4* src = (const float4*)(w2 + (size_t)kc * 64 * 256);
            float4* dst = (float4*)w2s;
            #pragma unroll
            for (int j = 0; j < 16; j++) dst[t + j * 256] = src[t + j * 256];
        }
        __syncthreads();
        int kg0 = kc * 64;
        #pragma unroll 4
        for (int k = 0; k < 64; k++) {
            const ulonglong2* wp = (const ulonglong2*)(w2s + (k << 8)) + (cg << 1);
            ulonglong2 wa = wp[0];
            ulonglong2 wb = wp[1];
            #pragma unroll
            for (int rr = 0; rr < 4; rr++) {
                unsigned long long hd = dup2(hs[(rbase + rr) * 256 + kg0 + k]);
                FMA2(acc[rr][0], hd, wa.x);
                FMA2(acc[rr][1], hd, wa.y);
                FMA2(acc[rr][2], hd, wb.x);
                FMA2(acc[rr][3], hd, wb.y);
            }
        }
    }

    float4* dst = (float4*)g_t[mat];
    #pragma unroll
    for (int rr = 0; rr < 4; rr++) {
        float2 p0 = unp2(acc[rr][0]), p1 = unp2(acc[rr][1]);
        float2 p2 = unp2(acc[rr][2]), p3 = unp2(acc[rr][3]);
        size_t rowb = (size_t)(r0 + rbase + rr) * 64;
        dst[rowb + cg * 2 + 0] = make_float4(p0.x, p0.y, p1.x, p1.y);
        dst[rowb + cg * 2 + 1] = make_float4(p2.x, p2.y, p3.x, p3.y);
    }
}

// ============================================================================
// A3: dm = spmm(A_e,t_e)+b2e - inter*(spmm(A_d,t_d)+b2d)  (4000 blocks x 512)
// ============================================================================
__global__ void __launch_bounds__(512) k3_gcn2(
    const float* __restrict__ b2e, const float* __restrict__ b2d,
    const float* __restrict__ inter) {
    __shared__ float ve[RCAP]; __shared__ int ce[RCAP];
    __shared__ float vd[RCAP]; __shared__ int cd[RCAP];
    __shared__ float4 part[512];

    int r = blockIdx.x;
    int t = threadIdx.x;

    int ne = g_elln[0][r], nd = g_elln[1][r];
    for (int i = t; i < ne; i += 512) { ve[i] = g_ellval[0][r * RCAP + i]; ce[i] = g_ellcol[0][r * RCAP + i]; }
    for (int i = t; i < nd; i += 512) { vd[i] = g_ellval[1][r * RCAP + i]; cd[i] = g_ellcol[1][r * RCAP + i]; }
    __syncthreads();

    int tt = t & 255;
    int eg = (tt & 63) << 2, seg = tt >> 6;
    int half = t >> 8;
    const float* vals = half ? vd : ve;
    const int*   cols = half ? cd : ce;
    const float* tsrc = half ? g_t[1] : g_t[0];
    int n = half ? nd : ne;

    float4 acc = {0.f, 0.f, 0.f, 0.f};
    for (int i = (n * seg) >> 2; i < (n * (seg + 1)) >> 2; i++) {
        float vv = vals[i];
        const float4 tv = *(const float4*)(tsrc + (size_t)cols[i] * 256 + eg);
        acc.x += vv * tv.x; acc.y += vv * tv.y; acc.z += vv * tv.z; acc.w += vv * tv.w;
    }
    part[t] = acc;
    __syncthreads();
    if (t < 64) {
        int eg2 = t << 2;
        float4 e0 = part[t], e1 = part[t + 64], e2 = part[t + 128], e3 = part[t + 192];
        float4 d0 = part[t + 256], d1 = part[t + 320], d2 = part[t + 384], d3 = part[t + 448];
        float iv = inter[0];
        float4 be = *(const float4*)(b2e + eg2);
        float4 bd = *(const float4*)(b2d + eg2);
        float4 o;
        o.x = (e0.x + e1.x + e2.x + e3.x + be.x) - iv * (d0.x + d1.x + d2.x + d3.x + bd.x);
        o.y = (e0.y + e1.y + e2.y + e3.y + be.y) - iv * (d0.y + d1.y + d2.y + d3.y + bd.y);
        o.z = (e0.z + e1.z + e2.z + e3.z + be.z) - iv * (d0.z + d1.z + d2.z + d3.z + bd.z);
        o.w = (e0.w + e1.w + e2.w + e3.w + be.w) - iv * (d0.w + d1.w + d2.w + d3.w + bd.w);
        *(float4*)(&g_dm[(size_t)r * 256 + eg2]) = o;
    }
}

// ============================================================================
// L5: fact1 partials [blocks 0..124] + fact2 per-visit partials [125..187]
// ============================================================================
__global__ void __launch_bounds__(256) k5_fact(const int* __restrict__ med) {
    int t = threadIdx.x, lane = t & 31, w = t >> 5, bid = blockIdx.x;

    if (bid < 125) {
        __shared__ float qys[256], sc[32], evs[32];
        int r0 = bid * 32;
        qys[t] = g_query[t];
        __syncthreads();
        const float4* qp = (const float4*)qys;
        #pragma unroll
        for (int jr = 0; jr < 4; jr++) {
            int j = w * 4 + jr;
            const float4* dp = (const float4*)(g_dm + (size_t)(r0 + j) * 256);
            float4 d0 = dp[lane], q0 = qp[lane];
            float4 d1 = dp[lane + 32], q1 = qp[lane + 32];
            float a = d0.x * q0.x + d0.y * q0.y + d0.z * q0.z + d0.w * q0.w
                    + d1.x * q1.x + d1.y * q1.y + d1.z * q1.z + d1.w * q1.w;
            a = warp_sum(a);
            if (lane == 0) sc[j] = a;
        }
        __syncthreads();
        if (t < 32) {
            float s0 = sc[t];
            float m = warp_max(s0);
            float e = expf(s0 - m);
            evs[t] = e;
            float s = warp_sum(e);
            if (t == 0) { g_m[bid] = m; g_esum[bid] = s; }
        }
        __syncthreads();
        float acc = 0.f;
        #pragma unroll 4
        for (int j = 0; j < 32; j++) acc += evs[j] * g_dm[(size_t)(r0 + j) * 256 + t];
        g_f1p[bid][t] = acc;
    } else {
        int i = bid - 125;
        __shared__ float vsv[64];
        __shared__ int cds[16];
        __shared__ unsigned mk;
        __shared__ float vmx;
        if (t < 63) {
            const float4 vp = *(const float4*)(g_vsp + t * 4);
            vsv[t] = (vp.x + vp.y) + (vp.z + vp.w);
        }
        if (t >= 64 && t < 80) cds[t - 64] = med[i * 16 + (t - 64)];
        __syncthreads();
        if (t == 0) {
            float m = -1e30f;
            for (int j = 0; j < 63; j++) m = fmaxf(m, vsv[j]);
            vmx = m;
            unsigned mm = 0;
            for (int k = 0; k < 16; k++) {
                int c = cds[k];
                bool dup = false;
                for (int j = 0; j < k; j++) dup |= (cds[j] == c);
                if (!dup) mm |= (1u << k);
            }
            mk = mm;
        }
        __syncthreads();
        float wv = expf(vsv[i] - vmx);
        unsigned m = mk;
        float acc = 0.f;
        #pragma unroll 4
        for (int k = 0; k < 16; k++)
            if ((m >> k) & 1u) acc += g_dm[(size_t)cds[k] * 256 + t];
        g_f2p[i][t] = wv * acc;
    }
}

// ============================================================================
// L6: assemble h, hidden = relu(h@w1+b1)    (16 blocks x 512)
// ============================================================================
__global__ void __launch_bounds__(512) k6_hidden(
    const float* __restrict__ w1, const float* __restrict__ b1) {
    __shared__ float h[768];
    __shared__ float sA[125], sB[125], vsv[63];
    __shared__ float part[512];
    __shared__ float gM_s, gden_s, vmax_s, vsuminv_s;
    int t = threadIdx.x;

    if (t < 125) { sA[t] = g_m[t]; sB[t] = g_esum[t]; }
    if (t >= 128 && t < 191) {
        int i = t - 128;
        const float4 vp = *(const float4*)(g_vsp + i * 4);
        vsv[i] = (vp.x + vp.y) + (vp.z + vp.w);
    }
    __syncthreads();
    if (t == 0) { float M = -1e30f; for (int b = 0; b < 125; b++) M = fmaxf(M, sA[b]); gM_s = M; }
    if (t == 1) { float m = -1e30f; for (int i = 0; i < 63; i++) m = fmaxf(m, vsv[i]); vmax_s = m; }
    __syncthreads();
    if (t < 125) sA[t] = expf(sA[t] - gM_s);
    __syncthreads();
    if (t == 0) { float s = 0.f; for (int b = 0; b < 125; b++) s += sA[b] * sB[b]; gden_s = 1.f / s; }
    if (t == 1) { float s = 0.f; for (int i = 0; i < 63; i++) s += expf(vsv[i] - vmax_s); vsuminv_s = 1.f / s; }
    __syncthreads();
    if (t < 256) {
        h[t] = g_query[t];
        float a = 0.f;
        for (int b = 0; b < 125; b++) a += sA[b] * g_f1p[b][t];
        h[256 + t] = a * gden_s;
        float f2 = 0.f;
        for (int i = 0; i < 63; i++) f2 += g_f2p[i][t];
        h[512 + t] = f2 * vsuminv_s;
    }
    __syncthreads();
    int o = blockIdx.x * 32 + (t & 31);
    int js = t >> 5;
    float acc = 0.f;
    int j0 = js * 48;
    #pragma unroll 8
    for (int j = j0; j < j0 + 48; j++) acc += h[j] * w1[(size_t)j * 512 + o];
    part[t] = acc;
    __syncthreads();
    if (t < 32) {
        float s = b1[o];
        #pragma unroll
        for (int m = 0; m < 16; m++) s += part[m * 32 + t];
        g_hid[o] = fmaxf(s, 0.f);
    }
}

// ============================================================================
// L7: output layer + sigmoid   (63 blocks x 512, o-split 8-way)
// ============================================================================
__global__ void __launch_bounds__(512) k7_out(
    const float* __restrict__ w2, const float* __restrict__ b2,
    float* __restrict__ out) {
    __shared__ float hid[512];
    __shared__ float part[512];
    int t = threadIdx.x;
    hid[t] = g_hid[t];
    __syncthreads();
    int tc = t & 63, os = t >> 6;
    int c = blockIdx.x * 64 + tc;
    float acc = 0.f;
    if (c < 4000) {
        int o0 = os * 64;
        #pragma unroll 8
        for (int o = o0; o < o0 + 64; o++) acc += hid[o] * w2[(size_t)o * 4000 + c];
    }
    part[t] = acc;
    __syncthreads();
    if (os == 0 && c < 4000) {
        float r = b2[c];
        #pragma unroll
        for (int m = 0; m < 8; m++) r += part[m * 64 + tc];
        out[c] = r;
        g_sp[c] = 1.f / (1.f + expf(-r));
    }
}

// ============================================================================
// L8: batch_neg from ddi ELL pattern (off-diag) + raw diagonal  (32 blocks)
// ============================================================================
__global__ void __launch_bounds__(128) k8_neg(
    const float* __restrict__ raw, float* __restrict__ out, int out_size) {
    __shared__ float sp[VMED];
    __shared__ float wred[4];
    int t = threadIdx.x, bid = blockIdx.x;
    for (int i = t; i < VMED; i += 128) sp[i] = g_sp[i];
    __syncthreads();
    float acc = 0.f;
    int r = bid * 125 + t;
    if (t < 125) {
        int n = g_elln[1][r];
        const int* cols = &g_ellcol[1][r * RCAP];
        float s = 0.f;
        for (int i = 0; i < n; i++) {
            int c = cols[i];
            if (c != r) s += sp[c];
        }
        s += raw[(size_t)r * 4000 + r] * sp[r];
        acc = s * sp[r];
    }
    float ws = warp_sum(acc);
    if ((t & 31) == 0) wred[t >> 5] = ws;
    __syncthreads();
    if (t == 0) {
        g_negp[bid] = (wred[0] + wred[1]) + (wred[2] + wred[3]);
        __threadfence();
        int old = atomicAdd(&g_ctr, 1);
        if (old == 31) {
            float s = 0.f;
            volatile float* np = g_negp;
            for (int b = 0; b < 32; b++) s += np[b];
            if (out_size > 4000) out[4000] = 0.0005f * s;
            g_ctr = 0;
        }
    }
}

// ---------------------------------------------------------------------------
extern "C" void kernel_launch(void* const* d_in, const int* in_sizes, int n_in,
                              void* d_out, int out_size) {
    const int*   proc    = (const int*)d_in[0];
    const int*   med     = (const int*)d_in[1];
    const float* emb     = (const float*)d_in[2];
    const float* conv_w  = (const float*)d_in[3];
    const float* conv_b  = (const float*)d_in[4];
    const float* wq      = (const float*)d_in[5];
    const float* wk      = (const float*)d_in[6];
    const float* wv      = (const float*)d_in[7];
    const float* wr      = (const float*)d_in[8];
    const float* alpha   = (const float*)d_in[9];
    const float* beta    = (const float*)d_in[10];
    const float* ehr_adj = (const float*)d_in[11];
    const float* ddi_adj = (const float*)d_in[12];
    const float* ddi_raw = (const float*)d_in[13];
    const float* ehr_w1  = (const float*)d_in[14];
    const float* ehr_b1  = (const float*)d_in[15];
    const float* ehr_w2  = (const float*)d_in[16];
    const float* ehr_b2  = (const float*)d_in[17];
    const float* ddi_w1  = (const float*)d_in[18];
    const float* ddi_b1  = (const float*)d_in[19];
    const float* ddi_w2  = (const float*)d_in[20];
    const float* ddi_b2  = (const float*)d_in[21];
    const float* inter   = (const float*)d_in[22];
    const float* out_w1  = (const float*)d_in[23];
    const float* out_b1  = (const float*)d_in[24];
    const float* out_w2  = (const float*)d_in[25];
    const float* out_b2  = (const float*)d_in[26];
    float* out = (float*)d_out;

    const int K2_SMEM = 96 * 1024;
    cudaFuncSetAttribute(k2_gemm,
                         cudaFuncAttributeMaxDynamicSharedMemorySize, K2_SMEM);

    // Fork a side stream for the light front chain (capture-legal pattern:
    // event fork off the capture stream, join before the consumer). Streams/
    // events are created per call; kernel_launch only runs a handful of times
    // (correctness + capture), so there is no unbounded resource growth.
    cudaStream_t s1;
    cudaEvent_t e0, e1;
    cudaStreamCreateWithFlags(&s1, cudaStreamNonBlocking);
    cudaEventCreateWithFlags(&e0, cudaEventDisableTiming);
    cudaEventCreateWithFlags(&e1, cudaEventDisableTiming);

    cudaEventRecord(e0, 0);
    cudaStreamWaitEvent(s1, e0, 0);

    // Branch B (side stream): embedding -> qkv -> gk -> query/visit scores
    kb_emb<<<64, 128, 0, s1>>>(proc, emb, conv_w, conv_b);
    kb_qkv<<<192, 256, 0, s1>>>(wq, wk, wv);
    kb_gk<<<1, 256, 0, s1>>>(alpha, beta);
    k4_feat<<<256, 256, 0, s1>>>(wr);
    cudaEventRecord(e1, s1);

    // Branch A (main stream): GCN spine
    k1_scan<<<2 * VMED, 512>>>(ehr_adj, ddi_adj, ehr_w1, ehr_b1, ddi_w1, ddi_b1);
    k2_gemm<<<250, 256, K2_SMEM>>>(ehr_w2, ddi_w2);
    k3_gcn2<<<VMED, 512>>>(ehr_b2, ddi_b2, inter);

    // Join, then tail
    cudaStreamWaitEvent(0, e1, 0);
    k5_fact<<<188, 256>>>(med);
    k6_hidden<<<16, 512>>>(out_w1, out_b1);
    k7_out<<<63, 512>>>(out_w2, out_b2, out);
    k8_neg<<<32, 128>>>(ddi_raw, out, out_size);
}

// round 15
// speedup vs baseline: 1.1756x; 1.1756x over previous
#include <cuda_runtime.h>

// ---------------------------------------------------------------------------
// FastRx_wo_Diag fp32. Round 14: exact revert to the 191us R11 build, with ONE
// change: kfc unbundled from k3; kfc+k4_feat run on a side stream overlapping
// k3's grid. kfa/kfb piggybacking and all numerics identical to R11.
// ---------------------------------------------------------------------------

#define RCAP 128
#define NV   64
#define VMED 4000

// ------------------------------ scratch ------------------------------------
__device__ float g_x[NV * 128];
__device__ float g_q[NV * 256];
__device__ float g_k[NV * 256];
__device__ float g_v[NV * 256];
__device__ float g_gk[256];
__device__ float g_query[256];
__device__ __align__(16) float g_vsp[NV * 4];   // visit-score partials (4/visit)

__device__ float g_ellval[2][VMED * RCAP];
__device__ int   g_ellcol[2][VMED * RCAP];
__device__ int   g_elln[2][VMED];
__device__ float g_h[2][VMED * 256];
__device__ float g_t[2][VMED * 256];
__device__ float g_dm[VMED * 256];

__device__ float g_f1p[125][256];
__device__ float g_esum[125];
__device__ float g_m[125];
__device__ float g_f2p[63][256];
__device__ float g_hid[512];
__device__ float g_sp[VMED];
__device__ float g_negp[32];
__device__ int   g_ctr;

// ------------------------------ helpers ------------------------------------
__device__ __forceinline__ float warp_sum(float v) {
    #pragma unroll
    for (int o = 16; o; o >>= 1) v += __shfl_xor_sync(0xffffffffu, v, o);
    return v;
}
__device__ __forceinline__ float warp_max(float v) {
    #pragma unroll
    for (int o = 16; o; o >>= 1) v = fmaxf(v, __shfl_xor_sync(0xffffffffu, v, o));
    return v;
}
__device__ __forceinline__ unsigned long long dup2(float x) {
    unsigned long long r;
    asm("mov.b64 %0, {%1, %1};" : "=l"(r) : "f"(x));
    return r;
}
__device__ __forceinline__ float2 unp2(unsigned long long v) {
    float2 f;
    asm("mov.b64 {%0, %1}, %2;" : "=f"(f.x), "=f"(f.y) : "l"(v));
    return f;
}
#define FMA2(acc, a, b) asm("fma.rn.f32x2 %0, %1, %2, %0;" : "+l"(acc) : "l"(a), "l"(b))

// ============================================================================
// L1: adjacency scan -> ELL + h = relu(A@w1+b1)   [blocks 0..7999]
//     + kfa embedding-mean + conv                 [blocks 8000..8063]
// ============================================================================
__global__ void __launch_bounds__(256) k1_scan_front(
    const float* __restrict__ ehr_adj, const float* __restrict__ ddi_adj,
    const float* __restrict__ ehr_w1, const float* __restrict__ ehr_b1,
    const float* __restrict__ ddi_w1, const float* __restrict__ ddi_b1,
    const int* __restrict__ pc, const float* __restrict__ emb,
    const float* __restrict__ cw, const float* __restrict__ cb) {

    __shared__ float val_s[RCAP];
    __shared__ int   col_s[RCAP];
    __shared__ int   woff[8];
    __shared__ int   nnz_s;
    __shared__ float4 part[256];
    __shared__ float xm[130];
    __shared__ int   cs[32];

    int bid = blockIdx.x;
    int t = threadIdx.x, lane = t & 31, w = t >> 5;

    if (bid >= 2 * VMED) {                 // ---- kfa branch ----
        int v = bid - 2 * VMED;
        if (t < 32) cs[t] = pc[v * 32 + t];
        __syncthreads();
        if (t < 128) {
            float a = 0.f;
            #pragma unroll 4
            for (int k = 0; k < 32; k++) a += emb[cs[k] * 128 + t];
            xm[t + 1] = a * (1.f / 32.f);
            if (t == 0) { xm[0] = 0.f; xm[129] = 0.f; }
        }
        __syncthreads();
        if (t < 128) {
            float w0 = cw[0], w1 = cw[1], w2 = cw[2], b = cb[0];
            g_x[v * 128 + t] = fmaxf(w0 * xm[t] + w1 * xm[t + 1] + w2 * xm[t + 2] + b, 0.f);
        }
        return;
    }

    int mat = (bid >= VMED) ? 1 : 0;
    int r = bid - mat * VMED;
    const float* adj = mat ? ddi_adj : ehr_adj;
    const float* w1  = mat ? ddi_w1  : ehr_w1;
    const float* b1  = mat ? ddi_b1  : ehr_b1;

    float arr[16];
    int cnt = 0;
    const float4* rowp = (const float4*)(adj + (size_t)r * 4000);
    if (t < 250) {
        #pragma unroll
        for (int j = 0; j < 4; j++) {
            float4 q = rowp[t * 4 + j];
            arr[j * 4 + 0] = q.x; arr[j * 4 + 1] = q.y;
            arr[j * 4 + 2] = q.z; arr[j * 4 + 3] = q.w;
        }
        #pragma unroll
        for (int j = 0; j < 16; j++) cnt += (arr[j] != 0.f);
    } else {
        #pragma unroll
        for (int j = 0; j < 16; j++) arr[j] = 0.f;
    }
    int incl = cnt;
    #pragma unroll
    for (int o = 1; o < 32; o <<= 1) {
        int x = __shfl_up_sync(0xffffffffu, incl, o);
        if (lane >= o) incl += x;
    }
    if (lane == 31) woff[w] = incl;
    __syncthreads();
    if (t == 0) {
        int s = 0;
        #pragma unroll
        for (int i = 0; i < 8; i++) { int c = woff[i]; woff[i] = s; s += c; }
        nnz_s = (s < RCAP) ? s : RCAP;
    }
    __syncthreads();
    int pos = woff[w] + incl - cnt;
    if (t < 250) {
        #pragma unroll
        for (int j = 0; j < 16; j++) {
            float vv = arr[j];
            if (vv != 0.f) {
                if (pos < RCAP) { val_s[pos] = vv; col_s[pos] = t * 16 + j; }
                pos++;
            }
        }
    }
    __syncthreads();
    int n = nnz_s;
    for (int i = t; i < n; i += 256) {
        g_ellval[mat][r * RCAP + i] = val_s[i];
        g_ellcol[mat][r * RCAP + i] = col_s[i];
    }
    if (t == 0) g_elln[mat][r] = n;

    // --- h = relu(spmm + b1): 4 nnz segments x 64 col-quads -----------------
    int eg = (t & 63) << 2;
    int seg = t >> 6;
    float4 acc = {0.f, 0.f, 0.f, 0.f};
    int i0 = (n * seg) >> 2, i1 = (n * (seg + 1)) >> 2;
    for (int i = i0; i < i1; i++) {
        float vv = val_s[i];
        const float4 wv = *(const float4*)(w1 + (size_t)col_s[i] * 256 + eg);
        acc.x += vv * wv.x; acc.y += vv * wv.y; acc.z += vv * wv.z; acc.w += vv * wv.w;
    }
    part[t] = acc;
    __syncthreads();
    if (seg == 0) {
        float4 p0 = part[t], p1 = part[t + 64], p2 = part[t + 128], p3 = part[t + 192];
        float4 bb = *(const float4*)(b1 + eg);
        float4 hh;
        hh.x = fmaxf(p0.x + p1.x + p2.x + p3.x + bb.x, 0.f);
        hh.y = fmaxf(p0.y + p1.y + p2.y + p3.y + bb.y, 0.f);
        hh.z = fmaxf(p0.z + p1.z + p2.z + p3.z + bb.z, 0.f);
        hh.w = fmaxf(p0.w + p1.w + p2.w + p3.w + bb.w, 0.f);
        *(float4*)(g_h[mat] + (size_t)r * 256 + eg) = hh;
    }
}

// ============================================================================
// L2: t = h @ w2 GEMM, M=32/block, w2 slab staged in smem  [blocks 0..249]
//     + kfb q,k,v = x @ W                                  [blocks 250..441]
// ============================================================================
__global__ void __launch_bounds__(256) k2_gemm_qkv(
    const float* __restrict__ ehr_w2, const float* __restrict__ ddi_w2,
    const float* __restrict__ wq, const float* __restrict__ wk,
    const float* __restrict__ wv) {
    extern __shared__ float dynsm[];
    __shared__ float xr[128];
    int t = threadIdx.x, bid = blockIdx.x;

    if (bid < 250) {                        // ---- GEMM tile ----
        float* hs  = dynsm;                 // 32*256 floats
        float* w2s = dynsm + 32 * 256;      // 64*256 floats
        int mat = bid / 125, r0 = (bid % 125) * 32;
        const float* w2 = mat ? ddi_w2 : ehr_w2;

        {
            const float4* src = (const float4*)(g_h[mat] + (size_t)r0 * 256);
            float4* dst = (float4*)hs;
            #pragma unroll
            for (int j = 0; j < 8; j++) dst[t + j * 256] = src[t + j * 256];
        }

        int cg = t & 31, rg = t >> 5;
        int rbase = rg * 4;
        unsigned long long acc[4][4];
        #pragma unroll
        for (int a = 0; a < 4; a++)
            #pragma unroll
            for (int b = 0; b < 4; b++) acc[a][b] = 0ULL;

        #pragma unroll 1
        for (int kc = 0; kc < 4; kc++) {
            __syncthreads();
            {
                const float4* src = (const float4*)(w2 + (size_t)kc * 64 * 256);
                float4* dst = (float4*)w2s;
                #pragma unroll
                for (int j = 0; j < 16; j++) dst[t + j * 256] = src[t + j * 256];
            }
            __syncthreads();
            int kg0 = kc * 64;
            #pragma unroll 4
            for (int k = 0; k < 64; k++) {
                const ulonglong2* wp = (const ulonglong2*)(w2s + (k << 8)) + (cg << 1);
                ulonglong2 wa = wp[0];
                ulonglong2 wb = wp[1];
                #pragma unroll
                for (int rr = 0; rr < 4; rr++) {
                    unsigned long long hd = dup2(hs[(rbase + rr) * 256 + kg0 + k]);
                    FMA2(acc[rr][0], hd, wa.x);
                    FMA2(acc[rr][1], hd, wa.y);
                    FMA2(acc[rr][2], hd, wb.x);
                    FMA2(acc[rr][3], hd, wb.y);
                }
            }
        }

        float4* dst = (float4*)g_t[mat];
        #pragma unroll
        for (int rr = 0; rr < 4; rr++) {
            float2 p0 = unp2(acc[rr][0]), p1 = unp2(acc[rr][1]);
            float2 p2 = unp2(acc[rr][2]), p3 = unp2(acc[rr][3]);
            size_t rowb = (size_t)(r0 + rbase + rr) * 64;
            dst[rowb + cg * 2 + 0] = make_float4(p0.x, p0.y, p1.x, p1.y);
            dst[rowb + cg * 2 + 1] = make_float4(p2.x, p2.y, p3.x, p3.y);
        }
    } else {                                // ---- kfb branch ----
        int b2 = bid - 250, v = b2 & 63, m = b2 >> 6;
        const float* W = (m == 0) ? wq : (m == 1) ? wk : wv;
        float* D = (m == 0) ? g_q : (m == 1) ? g_k : g_v;
        if (t < 128) xr[t] = g_x[v * 128 + t];
        __syncthreads();
        float a0 = 0.f, a1 = 0.f, a2 = 0.f, a3 = 0.f;
        #pragma unroll 8
        for (int f = 0; f < 128; f += 4) {
            a0 += xr[f]     * W[(f)     * 256 + t];
            a1 += xr[f + 1] * W[(f + 1) * 256 + t];
            a2 += xr[f + 2] * W[(f + 2) * 256 + t];
            a3 += xr[f + 3] * W[(f + 3) * 256 + t];
        }
        D[v * 256 + t] = (a0 + a1) + (a2 + a3);
    }
}

// ============================================================================
// Side stream: kfc fastformer global vectors   (1 block x 256)
// ============================================================================
__global__ void __launch_bounds__(256) kb_gk(
    const float* __restrict__ alpha, const float* __restrict__ beta) {
    __shared__ float m1[64], rd1[64], gqs[256], m2[64], rd2[64];
    const float scale = 0.0625f;
    int t = threadIdx.x, lane = t & 31, w = t >> 5;
    for (int rr = 0; rr < 8; rr++) {
        int r = w * 8 + rr;
        float z[8], mx = -1e30f;
        #pragma unroll
        for (int j = 0; j < 8; j++) {
            int e = lane + j * 32;
            z[j] = g_q[r * 256 + e] * alpha[e] * scale;
            mx = fmaxf(mx, z[j]);
        }
        mx = warp_max(mx);
        float s = 0.f;
        #pragma unroll
        for (int j = 0; j < 8; j++) s += expf(z[j] - mx);
        s = warp_sum(s);
        if (lane == 0) { m1[r] = mx; rd1[r] = 1.f / s; }
    }
    __syncthreads();
    {
        float a = alpha[t] * scale, acc = 0.f;
        for (int v = 0; v < 64; v++) {
            float q = g_q[v * 256 + t];
            acc += q * expf(q * a - m1[v]) * rd1[v];
        }
        gqs[t] = acc;
    }
    __syncthreads();
    for (int rr = 0; rr < 8; rr++) {
        int r = w * 8 + rr;
        float z[8], mx = -1e30f;
        #pragma unroll
        for (int j = 0; j < 8; j++) {
            int e = lane + j * 32;
            z[j] = gqs[e] * g_k[r * 256 + e] * beta[e] * scale;
            mx = fmaxf(mx, z[j]);
        }
        mx = warp_max(mx);
        float s = 0.f;
        #pragma unroll
        for (int j = 0; j < 8; j++) s += expf(z[j] - mx);
        s = warp_sum(s);
        if (lane == 0) { m2[r] = mx; rd2[r] = 1.f / s; }
    }
    __syncthreads();
    {
        float bsc = beta[t] * scale, gq_e = gqs[t], acc = 0.f;
        for (int v = 0; v < 64; v++) {
            float p = gq_e * g_k[v * 256 + t];
            acc += p * expf(p * bsc - m2[v]) * rd2[v];
        }
        g_gk[t] = acc;
    }
}

// ============================================================================
// L3: dm = spmm(A_e,t_e)+b2e - inter*(spmm(A_d,t_d)+b2d)  (4000 blocks x 512)
// ============================================================================
__global__ void __launch_bounds__(512) k3_gcn2(
    const float* __restrict__ b2e, const float* __restrict__ b2d,
    const float* __restrict__ inter) {
    __shared__ float ve[RCAP]; __shared__ int ce[RCAP];
    __shared__ float vd[RCAP]; __shared__ int cd[RCAP];
    __shared__ float4 part[512];

    int r = blockIdx.x;
    int t = threadIdx.x;

    int ne = g_elln[0][r], nd = g_elln[1][r];
    for (int i = t; i < ne; i += 512) { ve[i] = g_ellval[0][r * RCAP + i]; ce[i] = g_ellcol[0][r * RCAP + i]; }
    for (int i = t; i < nd; i += 512) { vd[i] = g_ellval[1][r * RCAP + i]; cd[i] = g_ellcol[1][r * RCAP + i]; }
    __syncthreads();

    int tt = t & 255;
    int eg = (tt & 63) << 2, seg = tt >> 6;
    int half = t >> 8;
    const float* vals = half ? vd : ve;
    const int*   cols = half ? cd : ce;
    const float* tsrc = half ? g_t[1] : g_t[0];
    int n = half ? nd : ne;

    float4 acc = {0.f, 0.f, 0.f, 0.f};
    for (int i = (n * seg) >> 2; i < (n * (seg + 1)) >> 2; i++) {
        float vv = vals[i];
        const float4 tv = *(const float4*)(tsrc + (size_t)cols[i] * 256 + eg);
        acc.x += vv * tv.x; acc.y += vv * tv.y; acc.z += vv * tv.z; acc.w += vv * tv.w;
    }
    part[t] = acc;
    __syncthreads();
    if (t < 64) {
        int eg2 = t << 2;
        float4 e0 = part[t], e1 = part[t + 64], e2 = part[t + 128], e3 = part[t + 192];
        float4 d0 = part[t + 256], d1 = part[t + 320], d2 = part[t + 384], d3 = part[t + 448];
        float iv = inter[0];
        float4 be = *(const float4*)(b2e + eg2);
        float4 bd = *(const float4*)(b2d + eg2);
        float4 o;
        o.x = (e0.x + e1.x + e2.x + e3.x + be.x) - iv * (d0.x + d1.x + d2.x + d3.x + bd.x);
        o.y = (e0.y + e1.y + e2.y + e3.y + be.y) - iv * (d0.y + d1.y + d2.y + d3.y + bd.y);
        o.z = (e0.z + e1.z + e2.z + e3.z + be.z) - iv * (d0.z + d1.z + d2.z + d3.z + bd.z);
        o.w = (e0.w + e1.w + e2.w + e3.w + be.w) - iv * (d0.w + d1.w + d2.w + d3.w + bd.w);
        *(float4*)(&g_dm[(size_t)r * 256 + eg2]) = o;
    }
}

// ============================================================================
// Side stream: feat cols + visit-score partials (256 blocks = 64 v x 4 chunks)
// ============================================================================
__global__ void __launch_bounds__(256) k4_feat(const float* __restrict__ wr) {
    __shared__ float gvr[256], gv63[256];
    __shared__ float pf[4][64], p63[4][64];
    __shared__ float red[2];
    int bid = blockIdx.x;
    int v = bid >> 2, ch = bid & 3;
    int t = threadIdx.x;
    {
        float gk = g_gk[t];
        gvr[t]  = gk * g_v[v * 256 + t];
        gv63[t] = gk * g_v[63 * 256 + t];
    }
    __syncthreads();
    int col = (ch << 6) + (t & 63), seg = t >> 6;
    float a = 0.f, b = 0.f;
    int e0 = seg * 64;
    #pragma unroll 8
    for (int e = e0; e < e0 + 64; e++) {
        float wv = wr[e * 256 + col];
        a += gvr[e] * wv;
        b += gv63[e] * wv;
    }
    pf[seg][t & 63] = a; p63[seg][t & 63] = b;
    __syncthreads();
    if (t < 64) {
        int c = (ch << 6) + t;
        float fr  = g_q[v * 256 + c]  + ((pf[0][t] + pf[1][t]) + (pf[2][t] + pf[3][t]));
        float f63 = g_q[63 * 256 + c] + ((p63[0][t] + p63[1][t]) + (p63[2][t] + p63[3][t]));
        if (v == 63) g_query[c] = fr;
        float p = warp_sum(fr * f63);
        if ((t & 31) == 0) red[t >> 5] = p;
    }
    __syncthreads();
    if (t == 0) g_vsp[v * 4 + ch] = red[0] + red[1];
}

// ============================================================================
// L5: fact1 partials [blocks 0..124] + fact2 per-visit partials [125..187]
// ============================================================================
__global__ void __launch_bounds__(256) k5_fact(const int* __restrict__ med) {
    int t = threadIdx.x, lane = t & 31, w = t >> 5, bid = blockIdx.x;

    if (bid < 125) {
        __shared__ float qys[256], sc[32], evs[32];
        int r0 = bid * 32;
        qys[t] = g_query[t];
        __syncthreads();
        const float4* qp = (const float4*)qys;
        #pragma unroll
        for (int jr = 0; jr < 4; jr++) {
            int j = w * 4 + jr;
            const float4* dp = (const float4*)(g_dm + (size_t)(r0 + j) * 256);
            float4 d0 = dp[lane], q0 = qp[lane];
            float4 d1 = dp[lane + 32], q1 = qp[lane + 32];
            float a = d0.x * q0.x + d0.y * q0.y + d0.z * q0.z + d0.w * q0.w
                    + d1.x * q1.x + d1.y * q1.y + d1.z * q1.z + d1.w * q1.w;
            a = warp_sum(a);
            if (lane == 0) sc[j] = a;
        }
        __syncthreads();
        if (t < 32) {
            float s0 = sc[t];
            float m = warp_max(s0);
            float e = expf(s0 - m);
            evs[t] = e;
            float s = warp_sum(e);
            if (t == 0) { g_m[bid] = m; g_esum[bid] = s; }
        }
        __syncthreads();
        float acc = 0.f;
        #pragma unroll 4
        for (int j = 0; j < 32; j++) acc += evs[j] * g_dm[(size_t)(r0 + j) * 256 + t];
        g_f1p[bid][t] = acc;
    } else {
        int i = bid - 125;
        __shared__ float vsv[64];
        __shared__ int cds[16];
        __shared__ unsigned mk;
        __shared__ float vmx;
        if (t < 63) {
            const float4 vp = *(const float4*)(g_vsp + t * 4);
            vsv[t] = (vp.x + vp.y) + (vp.z + vp.w);
        }
        if (t >= 64 && t < 80) cds[t - 64] = med[i * 16 + (t - 64)];
        __syncthreads();
        if (t == 0) {
            float m = -1e30f;
            for (int j = 0; j < 63; j++) m = fmaxf(m, vsv[j]);
            vmx = m;
            unsigned mm = 0;
            for (int k = 0; k < 16; k++) {
                int c = cds[k];
                bool dup = false;
                for (int j = 0; j < k; j++) dup |= (cds[j] == c);
                if (!dup) mm |= (1u << k);
            }
            mk = mm;
        }
        __syncthreads();
        float wv = expf(vsv[i] - vmx);
        unsigned m = mk;
        float acc = 0.f;
        #pragma unroll 4
        for (int k = 0; k < 16; k++)
            if ((m >> k) & 1u) acc += g_dm[(size_t)cds[k] * 256 + t];
        g_f2p[i][t] = wv * acc;
    }
}

// ============================================================================
// L6: assemble h, hidden = relu(h@w1+b1)    (16 blocks x 512)
// ============================================================================
__global__ void __launch_bounds__(512) k6_hidden(
    const float* __restrict__ w1, const float* __restrict__ b1) {
    __shared__ float h[768];
    __shared__ float sA[125], sB[125], vsv[63];
    __shared__ float part[512];
    __shared__ float gM_s, gden_s, vmax_s, vsuminv_s;
    int t = threadIdx.x;

    if (t < 125) { sA[t] = g_m[t]; sB[t] = g_esum[t]; }
    if (t >= 128 && t < 191) {
        int i = t - 128;
        const float4 vp = *(const float4*)(g_vsp + i * 4);
        vsv[i] = (vp.x + vp.y) + (vp.z + vp.w);
    }
    __syncthreads();
    if (t == 0) { float M = -1e30f; for (int b = 0; b < 125; b++) M = fmaxf(M, sA[b]); gM_s = M; }
    if (t == 1) { float m = -1e30f; for (int i = 0; i < 63; i++) m = fmaxf(m, vsv[i]); vmax_s = m; }
    __syncthreads();
    if (t < 125) sA[t] = expf(sA[t] - gM_s);
    __syncthreads();
    if (t == 0) { float s = 0.f; for (int b = 0; b < 125; b++) s += sA[b] * sB[b]; gden_s = 1.f / s; }
    if (t == 1) { float s = 0.f; for (int i = 0; i < 63; i++) s += expf(vsv[i] - vmax_s); vsuminv_s = 1.f / s; }
    __syncthreads();
    if (t < 256) {
        h[t] = g_query[t];
        float a = 0.f;
        for (int b = 0; b < 125; b++) a += sA[b] * g_f1p[b][t];
        h[256 + t] = a * gden_s;
        float f2 = 0.f;
        for (int i = 0; i < 63; i++) f2 += g_f2p[i][t];
        h[512 + t] = f2 * vsuminv_s;
    }
    __syncthreads();
    int o = blockIdx.x * 32 + (t & 31);
    int js = t >> 5;
    float acc = 0.f;
    int j0 = js * 48;
    #pragma unroll 8
    for (int j = j0; j < j0 + 48; j++) acc += h[j] * w1[(size_t)j * 512 + o];
    part[t] = acc;
    __syncthreads();
    if (t < 32) {
        float s = b1[o];
        #pragma unroll
        for (int m = 0; m < 16; m++) s += part[m * 32 + t];
        g_hid[o] = fmaxf(s, 0.f);
    }
}

// ============================================================================
// L7: output layer + sigmoid   (63 blocks x 512, o-split 8-way)
// ============================================================================
__global__ void __launch_bounds__(512) k7_out(
    const float* __restrict__ w2, const float* __restrict__ b2,
    float* __restrict__ out) {
    __shared__ float hid[512];
    __shared__ float part[512];
    int t = threadIdx.x;
    hid[t] = g_hid[t];
    __syncthreads();
    int tc = t & 63, os = t >> 6;
    int c = blockIdx.x * 64 + tc;
    float acc = 0.f;
    if (c < 4000) {
        int o0 = os * 64;
        #pragma unroll 8
        for (int o = o0; o < o0 + 64; o++) acc += hid[o] * w2[(size_t)o * 4000 + c];
    }
    part[t] = acc;
    __syncthreads();
    if (os == 0 && c < 4000) {
        float r = b2[c];
        #pragma unroll
        for (int m = 0; m < 8; m++) r += part[m * 64 + tc];
        out[c] = r;
        g_sp[c] = 1.f / (1.f + expf(-r));
    }
}

// ============================================================================
// L8: batch_neg from ddi ELL pattern (off-diag) + raw diagonal  (32 blocks)
// ============================================================================
__global__ void __launch_bounds__(128) k8_neg(
    const float* __restrict__ raw, float* __restrict__ out, int out_size) {
    __shared__ float sp[VMED];
    __shared__ float wred[4];
    int t = threadIdx.x, bid = blockIdx.x;
    for (int i = t; i < VMED; i += 128) sp[i] = g_sp[i];
    __syncthreads();
    float acc = 0.f;
    int r = bid * 125 + t;
    if (t < 125) {
        int n = g_elln[1][r];
        const int* cols = &g_ellcol[1][r * RCAP];
        float s = 0.f;
        for (int i = 0; i < n; i++) {
            int c = cols[i];
            if (c != r) s += sp[c];
        }
        s += raw[(size_t)r * 4000 + r] * sp[r];
        acc = s * sp[r];
    }
    float ws = warp_sum(acc);
    if ((t & 31) == 0) wred[t >> 5] = ws;
    __syncthreads();
    if (t == 0) {
        g_negp[bid] = (wred[0] + wred[1]) + (wred[2] + wred[3]);
        __threadfence();
        int old = atomicAdd(&g_ctr, 1);
        if (old == 31) {
            float s = 0.f;
            volatile float* np = g_negp;
            for (int b = 0; b < 32; b++) s += np[b];
            if (out_size > 4000) out[4000] = 0.0005f * s;
            g_ctr = 0;
        }
    }
}

// ---------------------------------------------------------------------------
extern "C" void kernel_launch(void* const* d_in, const int* in_sizes, int n_in,
                              void* d_out, int out_size) {
    const int*   proc    = (const int*)d_in[0];
    const int*   med     = (const int*)d_in[1];
    const float* emb     = (const float*)d_in[2];
    const float* conv_w  = (const float*)d_in[3];
    const float* conv_b  = (const float*)d_in[4];
    const float* wq      = (const float*)d_in[5];
    const float* wk      = (const float*)d_in[6];
    const float* wv      = (const float*)d_in[7];
    const float* wr      = (const float*)d_in[8];
    const float* alpha   = (const float*)d_in[9];
    const float* beta    = (const float*)d_in[10];
    const float* ehr_adj = (const float*)d_in[11];
    const float* ddi_adj = (const float*)d_in[12];
    const float* ddi_raw = (const float*)d_in[13];
    const float* ehr_w1  = (const float*)d_in[14];
    const float* ehr_b1  = (const float*)d_in[15];
    const float* ehr_w2  = (const float*)d_in[16];
    const float* ehr_b2  = (const float*)d_in[17];
    const float* ddi_w1  = (const float*)d_in[18];
    const float* ddi_b1  = (const float*)d_in[19];
    const float* ddi_w2  = (const float*)d_in[20];
    const float* ddi_b2  = (const float*)d_in[21];
    const float* inter   = (const float*)d_in[22];
    const float* out_w1  = (const float*)d_in[23];
    const float* out_b1  = (const float*)d_in[24];
    const float* out_w2  = (const float*)d_in[25];
    const float* out_b2  = (const float*)d_in[26];
    float* out = (float*)d_out;

    const int K2_SMEM = 96 * 1024;
    cudaFuncSetAttribute(k2_gemm_qkv,
                         cudaFuncAttributeMaxDynamicSharedMemorySize, K2_SMEM);

    // Capture-legal fork: kfc + k4_feat (depend only on k2's qkv) run on a
    // side stream concurrent with k3; join before k5.
    cudaStream_t s1;
    cudaEvent_t e0, e1;
    cudaStreamCreateWithFlags(&s1, cudaStreamNonBlocking);
    cudaEventCreateWithFlags(&e0, cudaEventDisableTiming);
    cudaEventCreateWithFlags(&e1, cudaEventDisableTiming);

    k1_scan_front<<<2 * VMED + 64, 256>>>(ehr_adj, ddi_adj, ehr_w1, ehr_b1,
                                          ddi_w1, ddi_b1, proc, emb, conv_w, conv_b);
    k2_gemm_qkv<<<442, 256, K2_SMEM>>>(ehr_w2, ddi_w2, wq, wk, wv);

    cudaEventRecord(e0, 0);
    cudaStreamWaitEvent(s1, e0, 0);

    // Side stream: gk -> query/visit scores (overlaps k3)
    kb_gk<<<1, 256, 0, s1>>>(alpha, beta);
    k4_feat<<<256, 256, 0, s1>>>(wr);
    cudaEventRecord(e1, s1);

    // Main stream: k3 concurrent with side chain
    k3_gcn2<<<VMED, 512>>>(ehr_b2, ddi_b2, inter);

    cudaStreamWaitEvent(0, e1, 0);
    k5_fact<<<188, 256>>>(med);
    k6_hidden<<<16, 512>>>(out_w1, out_b1);
    k7_out<<<63, 512>>>(out_w2, out_b2, out);
    k8_neg<<<32, 128>>>(ddi_raw, out, out_size);
}